// round 11
// baseline (speedup 1.0000x reference)
#include <cuda_runtime.h>
#include <cuda_fp16.h>

#define NN 100000
#define NE 1600000
#define F 64
#define G 64
#define EPS 1e-5f

// ---------------- scratch (device globals) ----------------------------------
__device__ float2 g_degcnt[NN];            // .x = weighted deg, .y = count
__device__ float g_dis[NN];
__device__ int2  g_rowinfo[NN];            // {start, count}
__device__ int   g_rank[NE];               // per-edge slot within its dst row
__device__ int   g_total;
__device__ unsigned g_csr[NE];             // bits[31:17] = fp16 norm (sign=0), [16:0] = src
__device__ __half g_xh[NN * F];            // x in fp16
__device__ __half g_h1[NN * F];
__device__ __half g_h2[NN * F];
__device__ __half g_h3[NN * F];
__device__ __half g_whT[4 * 64 * 72];      // W fp16, n-major [m][n][k], stride 72
__device__ float g_out[NN * F];
__device__ float g_sum[G * F];
__device__ float g_sumsq[G * F];
__device__ float g_cnt[G];
__device__ float g_scale[G * F];
__device__ float g_shift[G * F];
__device__ float g_psum[G * F];
__device__ float g_pmax[G * F];

// ---------------- fused init: zero scratch + x->fp16 + W->fp16 n-major ---------
__global__ void k_init(const float2* __restrict__ x, const float* __restrict__ W) {
    int i = blockIdx.x * blockDim.x + threadIdx.x;
    int st = gridDim.x * blockDim.x;
    for (int j = i; j < NN * F / 2; j += st)
        reinterpret_cast<__half2*>(g_xh)[j] = __float22half2_rn(x[j]);
    for (int j = i; j < NN; j += st) g_degcnt[j] = make_float2(0.f, 0.f);
    for (int j = i; j < G * F; j += st) { g_sum[j] = 0.f; g_sumsq[j] = 0.f; g_psum[j] = 0.f; g_pmax[j] = 0.f; }
    for (int j = i; j < G; j += st) g_cnt[j] = 0.f;
    for (int j = i; j < 4 * 64 * 64; j += st) {
        int m = j >> 12;
        int k = (j >> 6) & 63;
        int n = j & 63;
        g_whT[m * 64 * 72 + n * 72 + k] = __float2half_rn(W[j]);
    }
    if (i == 0) g_total = 0;
}

// ---------------- degree + count; atomic return gives per-edge rank -----------
__global__ void k_deg(const int* __restrict__ dst, const float* __restrict__ w) {
    int e = blockIdx.x * blockDim.x + threadIdx.x;
    if (e < NE) {
        float2 old = atomicAdd(&g_degcnt[dst[e]], make_float2(w[e], 1.f));
        g_rank[e] = (int)old.y;
    }
}

// ---------------- offsets: block scan + global cursor (order-free CSR) --------
__global__ void k_offsets() {
    __shared__ int s[256];
    __shared__ int sbase;
    int tid = threadIdx.x;
    int i = blockIdx.x * 256 + tid;
    float2 dc = (i < NN) ? g_degcnt[i] : make_float2(0.f, 0.f);
    int c = (int)dc.y;
    s[tid] = c;
    __syncthreads();
    #pragma unroll
    for (int off = 1; off < 256; off <<= 1) {
        int t = (tid >= off) ? s[tid - off] : 0;
        __syncthreads();
        s[tid] += t;
        __syncthreads();
    }
    if (tid == 255) sbase = atomicAdd(&g_total, s[255]);
    __syncthreads();
    if (i < NN) {
        int start = sbase + s[tid] - c;
        g_rowinfo[i] = make_int2(start, c);
        g_dis[i] = dc.x > 0.f ? rsqrtf(dc.x) : 0.f;
    }
}

// ---------------- scatter edges into packed 4B CSR (no atomic) -----------------
__global__ void k_scatter(const int* __restrict__ src, const int* __restrict__ dst,
                          const float* __restrict__ w) {
    int e = blockIdx.x * blockDim.x + threadIdx.x;
    if (e >= NE) return;
    int s = src[e];
    int d = dst[e];
    float nw = g_dis[s] * w[e] * g_dis[d];           // >= 0, sign bit of fp16 is 0
    unsigned short hb = __half_as_ushort(__float2half_rn(nw));
    int p = g_rowinfo[d].x + g_rank[e];
    g_csr[p] = ((unsigned)hb << 17) | (unsigned)s;
}

// ---------------- gather hop (fp16 rows): 8 lanes/node, unroll 16 -------------
__device__ __forceinline__ void acc_half8(float* acc, float w, uint4 v) {
    float2 f0 = __half22float2(*reinterpret_cast<__half2*>(&v.x));
    float2 f1 = __half22float2(*reinterpret_cast<__half2*>(&v.y));
    float2 f2 = __half22float2(*reinterpret_cast<__half2*>(&v.z));
    float2 f3 = __half22float2(*reinterpret_cast<__half2*>(&v.w));
    acc[0] = fmaf(w, f0.x, acc[0]); acc[1] = fmaf(w, f0.y, acc[1]);
    acc[2] = fmaf(w, f1.x, acc[2]); acc[3] = fmaf(w, f1.y, acc[3]);
    acc[4] = fmaf(w, f2.x, acc[4]); acc[5] = fmaf(w, f2.y, acc[5]);
    acc[6] = fmaf(w, f3.x, acc[6]); acc[7] = fmaf(w, f3.y, acc[7]);
}
__device__ __forceinline__ float csr_w(unsigned r) {
    return __half2float(__ushort_as_half((unsigned short)(r >> 17)));
}

__global__ void k_gather(const uint4* __restrict__ hprev, uint4* __restrict__ hcur) {
    int gid = blockIdx.x * blockDim.x + threadIdx.x;
    int n = gid >> 3;
    int q = gid & 7;
    if (n >= NN) return;
    int2 ri = g_rowinfo[n];
    int e = ri.x;
    int end = e + ri.y;
    float acc[8] = {0.f, 0.f, 0.f, 0.f, 0.f, 0.f, 0.f, 0.f};
    for (; e + 16 <= end; e += 16) {
        unsigned r[16];
        #pragma unroll
        for (int j = 0; j < 16; j++) r[j] = g_csr[e + j];
        uint4 v[16];
        #pragma unroll
        for (int j = 0; j < 16; j++) v[j] = hprev[(int)(r[j] & 0x1FFFFu) * 8 + q];
        #pragma unroll
        for (int j = 0; j < 16; j++)
            acc_half8(acc, csr_w(r[j]), v[j]);
    }
    for (; e + 8 <= end; e += 8) {
        unsigned r[8];
        #pragma unroll
        for (int j = 0; j < 8; j++) r[j] = g_csr[e + j];
        uint4 v[8];
        #pragma unroll
        for (int j = 0; j < 8; j++) v[j] = hprev[(int)(r[j] & 0x1FFFFu) * 8 + q];
        #pragma unroll
        for (int j = 0; j < 8; j++)
            acc_half8(acc, csr_w(r[j]), v[j]);
    }
    for (; e + 4 <= end; e += 4) {
        unsigned r[4];
        #pragma unroll
        for (int j = 0; j < 4; j++) r[j] = g_csr[e + j];
        uint4 v[4];
        #pragma unroll
        for (int j = 0; j < 4; j++) v[j] = hprev[(int)(r[j] & 0x1FFFFu) * 8 + q];
        #pragma unroll
        for (int j = 0; j < 4; j++)
            acc_half8(acc, csr_w(r[j]), v[j]);
    }
    for (; e < end; e++) {
        unsigned r0 = g_csr[e];
        uint4 v0 = hprev[(int)(r0 & 0x1FFFFu) * 8 + q];
        acc_half8(acc, csr_w(r0), v0);
    }
    uint4 o;
    __half2 o0 = __float22half2_rn(make_float2(acc[0], acc[1]));
    __half2 o1 = __float22half2_rn(make_float2(acc[2], acc[3]));
    __half2 o2 = __float22half2_rn(make_float2(acc[4], acc[5]));
    __half2 o3 = __float22half2_rn(make_float2(acc[6], acc[7]));
    o.x = *reinterpret_cast<unsigned*>(&o0);
    o.y = *reinterpret_cast<unsigned*>(&o1);
    o.z = *reinterpret_cast<unsigned*>(&o2);
    o.w = *reinterpret_cast<unsigned*>(&o3);
    hcur[n * 8 + q] = o;
}

// ---------------- tensor-core 4-way matmul: out = b + sum_m Xm @ Wm -------------
#define WT_STRIDE 72
__global__ void __launch_bounds__(256) k_mat4_mma(
        const __half* __restrict__ X0, const __half* __restrict__ X1,
        const __half* __restrict__ X2, const __half* __restrict__ X3,
        const float* __restrict__ bias, float* __restrict__ out) {
    __shared__ __half sW[4 * 64 * WT_STRIDE];   // 36864 B
    int tid = threadIdx.x;

    {
        const uint4* srcp = (const uint4*)g_whT;
        uint4* dstp = (uint4*)sW;
        #pragma unroll
        for (int i = 0; i < 9; i++) dstp[tid + i * 256] = srcp[tid + i * 256];
    }
    __syncthreads();

    int warp = tid >> 5;
    int lane = tid & 31;
    int rowbase = blockIdx.x * 128 + warp * 16;
    int r1 = rowbase + (lane >> 2);
    int r2 = r1 + 8;
    int qk = (lane & 3) * 2;
    int lr1 = min(r1, NN - 1);
    int lr2 = min(r2, NN - 1);

    unsigned swbase = (unsigned)__cvta_generic_to_shared(sW);
    unsigned rowptr = swbase + (lane & 7) * 144 + ((lane >> 3) & 1) * 16
                    + ((lane >> 4) & 1) * 1152;

    float c[8][4];
    #pragma unroll
    for (int nt = 0; nt < 8; nt++) {
        float2 bv = *reinterpret_cast<const float2*>(&bias[nt * 8 + qk]);
        c[nt][0] = bv.x; c[nt][1] = bv.y; c[nt][2] = bv.x; c[nt][3] = bv.y;
    }

    const __half* Xs[4] = {X0, X1, X2, X3};
    #pragma unroll
    for (int m = 0; m < 4; m++) {
        const __half* Xm = Xs[m];
        unsigned mbase = rowptr + m * 9216;
        #pragma unroll
        for (int ks = 0; ks < 4; ks++) {
            unsigned a0 = *reinterpret_cast<const unsigned*>(&Xm[lr1 * 64 + ks * 16 + qk]);
            unsigned a1 = *reinterpret_cast<const unsigned*>(&Xm[lr2 * 64 + ks * 16 + qk]);
            unsigned a2 = *reinterpret_cast<const unsigned*>(&Xm[lr1 * 64 + ks * 16 + qk + 8]);
            unsigned a3 = *reinterpret_cast<const unsigned*>(&Xm[lr2 * 64 + ks * 16 + qk + 8]);
            #pragma unroll
            for (int np = 0; np < 4; np++) {
                unsigned b0, b1, b2, b3;
                unsigned addr = mbase + np * 2304 + ks * 32;
                asm volatile(
                    "ldmatrix.sync.aligned.m8n8.x4.shared.b16 {%0,%1,%2,%3}, [%4];"
                    : "=r"(b0), "=r"(b1), "=r"(b2), "=r"(b3) : "r"(addr));
                int nt = np * 2;
                asm volatile(
                    "mma.sync.aligned.m16n8k16.row.col.f32.f16.f16.f32 "
                    "{%0,%1,%2,%3}, {%4,%5,%6,%7}, {%8,%9}, {%0,%1,%2,%3};"
                    : "+f"(c[nt][0]), "+f"(c[nt][1]), "+f"(c[nt][2]), "+f"(c[nt][3])
                    : "r"(a0), "r"(a1), "r"(a2), "r"(a3), "r"(b0), "r"(b1));
                asm volatile(
                    "mma.sync.aligned.m16n8k16.row.col.f32.f16.f16.f32 "
                    "{%0,%1,%2,%3}, {%4,%5,%6,%7}, {%8,%9}, {%0,%1,%2,%3};"
                    : "+f"(c[nt+1][0]), "+f"(c[nt+1][1]), "+f"(c[nt+1][2]), "+f"(c[nt+1][3])
                    : "r"(a0), "r"(a1), "r"(a2), "r"(a3), "r"(b2), "r"(b3));
            }
        }
    }

    bool s1 = (r1 < NN), s2 = (r2 < NN);
    #pragma unroll
    for (int nt = 0; nt < 8; nt++) {
        if (s1) *reinterpret_cast<float2*>(&out[r1 * 64 + nt * 8 + qk]) =
            make_float2(c[nt][0], c[nt][1]);
        if (s2) *reinterpret_cast<float2*>(&out[r2 * 64 + nt * 8 + qk]) =
            make_float2(c[nt][2], c[nt][3]);
    }
}

// ---------------- GraphNorm stats ----------------------------------------------
__global__ void k_stats(const float* __restrict__ out, const int* __restrict__ batch) {
    int f = threadIdx.x & 63;
    int rg = threadIdx.x >> 6;
    int row0 = blockIdx.x * 256;
    int rend = min(row0 + 256, NN);
    float s = 0.f, sq = 0.f, c = 0.f;
    int curg = -1;
    for (int r = row0 + rg; r < rend; r += 4) {
        int g = batch[r];
        if (g != curg) {
            if (curg >= 0) {
                atomicAdd(&g_sum[curg * 64 + f], s);
                atomicAdd(&g_sumsq[curg * 64 + f], sq);
                if (f == 0) atomicAdd(&g_cnt[curg], c);
            }
            curg = g; s = 0.f; sq = 0.f; c = 0.f;
        }
        float v = out[r * 64 + f];
        s += v; sq += v * v; c += 1.f;
    }
    if (curg >= 0) {
        atomicAdd(&g_sum[curg * 64 + f], s);
        atomicAdd(&g_sumsq[curg * 64 + f], sq);
        if (f == 0) atomicAdd(&g_cnt[curg], c);
    }
}

// ---------------- per-(g,f) scale/shift ------------------------------------------
__global__ void k_prep(const float* __restrict__ gn_w, const float* __restrict__ gn_b,
                       const float* __restrict__ gn_ms) {
    int idx = blockIdx.x * blockDim.x + threadIdx.x;
    if (idx >= G * F) return;
    int g = idx >> 6, f = idx & 63;
    float cnt = fmaxf(g_cnt[g], 1.f);
    float m = g_sum[idx] / cnt;
    float ms = m * gn_ms[f];
    float var = g_sumsq[idx] / cnt - ms * (2.f * m - ms);
    var = fmaxf(var, 0.f);
    float sc = gn_w[f] * rsqrtf(var + EPS);
    g_scale[idx] = sc;
    g_shift[idx] = gn_b[f] - ms * sc;
}

// ---------------- normalize + residual + relu + pooling ---------------------------
__global__ void k_final(const float* __restrict__ out, const float* __restrict__ x,
                        const int* __restrict__ batch, float* __restrict__ demb) {
    int f = threadIdx.x & 63;
    int rg = threadIdx.x >> 6;
    int row0 = blockIdx.x * 256;
    int rend = min(row0 + 256, NN);
    float s = 0.f, mx = 0.f;
    int curg = -1;
    float sc = 0.f, sh = 0.f;
    for (int r = row0 + rg; r < rend; r += 4) {
        int g = batch[r];
        if (g != curg) {
            if (curg >= 0) {
                atomicAdd(&g_psum[curg * 64 + f], s);
                atomicMax(reinterpret_cast<int*>(&g_pmax[curg * 64 + f]), __float_as_int(mx));
            }
            curg = g; s = 0.f; mx = 0.f;
            sc = g_scale[g * 64 + f];
            sh = g_shift[g * 64 + f];
        }
        float v = out[r * 64 + f] * sc + sh + x[r * 64 + f];
        v = fmaxf(v, 0.f);
        demb[r * 64 + f] = v;
        s += v;
        mx = fmaxf(mx, v);
    }
    if (curg >= 0) {
        atomicAdd(&g_psum[curg * 64 + f], s);
        atomicMax(reinterpret_cast<int*>(&g_pmax[curg * 64 + f]), __float_as_int(mx));
    }
}

// ---------------- flat output: [G, 2F] ---------------------------------------------
__global__ void k_flat(float* __restrict__ flat) {
    int idx = blockIdx.x * blockDim.x + threadIdx.x;
    if (idx >= G * 2 * F) return;
    int g = idx >> 7, j = idx & 127;
    float cnt = fmaxf(g_cnt[g], 1.f);
    flat[idx] = (j < 64) ? (g_psum[g * 64 + j] / cnt) : g_pmax[g * 64 + (j - 64)];
}

// ---------------- launch -------------------------------------------------------------
extern "C" void kernel_launch(void* const* d_in, const int* in_sizes, int n_in,
                              void* d_out, int out_size) {
    const float* x     = (const float*)d_in[0];
    const int*   ei    = (const int*)d_in[1];
    const int*   batch = (const int*)d_in[2];
    const float* ew    = (const float*)d_in[3];
    const float* W     = (const float*)d_in[4];
    const float* bias  = (const float*)d_in[5];
    const float* gn_w  = (const float*)d_in[6];
    const float* gn_b  = (const float*)d_in[7];
    const float* gn_ms = (const float*)d_in[8];

    float* demb = (float*)d_out;
    float* flat = (float*)d_out + (size_t)NN * F;

    const int* src = ei;
    const int* dst = ei + NE;

    __half *pxh, *ph1, *ph2, *ph3;
    float *pout;
    cudaGetSymbolAddress((void**)&pxh, g_xh);
    cudaGetSymbolAddress((void**)&ph1, g_h1);
    cudaGetSymbolAddress((void**)&ph2, g_h2);
    cudaGetSymbolAddress((void**)&ph3, g_h3);
    cudaGetSymbolAddress((void**)&pout, g_out);

    k_init<<<4096, 256>>>((const float2*)x, W);
    k_deg<<<(NE + 255) / 256, 256>>>(dst, ew);
    k_offsets<<<(NN + 255) / 256, 256>>>();
    k_scatter<<<(NE + 255) / 256, 256>>>(src, dst, ew);

    int gat_blocks = (NN * 8 + 255) / 256;
    k_gather<<<gat_blocks, 256>>>((const uint4*)pxh, (uint4*)ph1);
    k_gather<<<gat_blocks, 256>>>((const uint4*)ph1, (uint4*)ph2);
    k_gather<<<gat_blocks, 256>>>((const uint4*)ph2, (uint4*)ph3);

    int mat_blocks = (NN + 127) / 128;
    k_mat4_mma<<<mat_blocks, 256>>>(pxh, ph1, ph2, ph3, bias, pout);

    int row_blocks = (NN + 255) / 256;
    k_stats<<<row_blocks, 256>>>(pout, batch);
    k_prep<<<(G * F + 255) / 256, 256>>>(gn_w, gn_b, gn_ms);
    k_final<<<row_blocks, 256>>>(pout, x, batch, demb);
    k_flat<<<(G * 2 * F + 255) / 256, 256>>>(flat);
}

// round 12
// speedup vs baseline: 1.2178x; 1.2178x over previous
#include <cuda_runtime.h>
#include <cuda_fp16.h>

#define NN 100000
#define NE 1600000
#define F 64
#define G 64
#define EPS 1e-5f

// ---------------- scratch (device globals) ----------------------------------
__device__ float2 g_degcnt[NN];            // .x = weighted deg, .y = count
__device__ float g_dis[NN];
__device__ int2  g_rowinfo[NN];            // {start, count}
__device__ int   g_rank[NE];               // per-edge slot within its dst row
__device__ int   g_total;
__device__ unsigned g_csr[NE];             // bits[31:17] = fp16 norm (sign=0), [16:0] = src
__device__ __half g_xh[NN * F];            // x in fp16
__device__ __half g_h1[NN * F];
__device__ __half g_h2[NN * F];
__device__ __half g_h3[NN * F];
__device__ __half g_whT[4 * 64 * 72];      // W fp16, n-major [m][n][k], stride 72
__device__ float g_out[NN * F];
__device__ float g_sum[G * F];
__device__ float g_sumsq[G * F];
__device__ float g_cnt[G];
__device__ float g_scale[G * F];
__device__ float g_shift[G * F];
__device__ float g_psum[G * F];
__device__ float g_pmax[G * F];

// ---------------- tiny zero: only what k_deg needs ----------------------------
__global__ void k_zero() {
    int i = blockIdx.x * blockDim.x + threadIdx.x;
    int st = gridDim.x * blockDim.x;
    for (int j = i; j < NN; j += st) g_degcnt[j] = make_float2(0.f, 0.f);
    if (i == 0) g_total = 0;
}

// ---------------- degree+rank, fused with conversions & small zeroing ---------
__global__ void k_deg(const int* __restrict__ dst, const float* __restrict__ w,
                      const float2* __restrict__ x, const float* __restrict__ W) {
    int i = blockIdx.x * blockDim.x + threadIdx.x;
    int st = gridDim.x * blockDim.x;                // 1.6M threads
    if (i < NE) {
        float2 old = atomicAdd(&g_degcnt[dst[i]], make_float2(w[i], 1.f));
        g_rank[i] = (int)old.y;
    }
    // independent streaming work rides under the atomic latency:
    for (int j = i; j < NN * F / 2; j += st)
        reinterpret_cast<__half2*>(g_xh)[j] = __float22half2_rn(x[j]);
    if (i < G * F) {
        g_sum[i] = 0.f; g_sumsq[i] = 0.f; g_psum[i] = 0.f; g_pmax[i] = 0.f;
        if (i < G) g_cnt[i] = 0.f;
    }
    if (i < 4 * 64 * 64) {
        int m = i >> 12;
        int k = (i >> 6) & 63;
        int n = i & 63;
        g_whT[m * 64 * 72 + n * 72 + k] = __float2half_rn(W[i]);
    }
}

// ---------------- offsets: block scan + global cursor (order-free CSR) --------
__global__ void k_offsets() {
    __shared__ int s[256];
    __shared__ int sbase;
    int tid = threadIdx.x;
    int i = blockIdx.x * 256 + tid;
    float2 dc = (i < NN) ? g_degcnt[i] : make_float2(0.f, 0.f);
    int c = (int)dc.y;
    s[tid] = c;
    __syncthreads();
    #pragma unroll
    for (int off = 1; off < 256; off <<= 1) {
        int t = (tid >= off) ? s[tid - off] : 0;
        __syncthreads();
        s[tid] += t;
        __syncthreads();
    }
    if (tid == 255) sbase = atomicAdd(&g_total, s[255]);
    __syncthreads();
    if (i < NN) {
        int start = sbase + s[tid] - c;
        g_rowinfo[i] = make_int2(start, c);
        g_dis[i] = dc.x > 0.f ? rsqrtf(dc.x) : 0.f;
    }
}

// ---------------- scatter edges into packed 4B CSR (no atomic) -----------------
__global__ void k_scatter(const int* __restrict__ src, const int* __restrict__ dst,
                          const float* __restrict__ w) {
    int e = blockIdx.x * blockDim.x + threadIdx.x;
    if (e >= NE) return;
    int s = src[e];
    int d = dst[e];
    float nw = g_dis[s] * w[e] * g_dis[d];           // >= 0, sign bit of fp16 is 0
    unsigned short hb = __half_as_ushort(__float2half_rn(nw));
    int p = g_rowinfo[d].x + g_rank[e];
    g_csr[p] = ((unsigned)hb << 17) | (unsigned)s;
}

// ---------------- gather hop (fp16 rows): 8 lanes/node, LDG.128, unroll 8 -----
__device__ __forceinline__ void acc_half8(float* acc, float w, uint4 v) {
    float2 f0 = __half22float2(*reinterpret_cast<__half2*>(&v.x));
    float2 f1 = __half22float2(*reinterpret_cast<__half2*>(&v.y));
    float2 f2 = __half22float2(*reinterpret_cast<__half2*>(&v.z));
    float2 f3 = __half22float2(*reinterpret_cast<__half2*>(&v.w));
    acc[0] = fmaf(w, f0.x, acc[0]); acc[1] = fmaf(w, f0.y, acc[1]);
    acc[2] = fmaf(w, f1.x, acc[2]); acc[3] = fmaf(w, f1.y, acc[3]);
    acc[4] = fmaf(w, f2.x, acc[4]); acc[5] = fmaf(w, f2.y, acc[5]);
    acc[6] = fmaf(w, f3.x, acc[6]); acc[7] = fmaf(w, f3.y, acc[7]);
}
__device__ __forceinline__ float csr_w(unsigned r) {
    return __half2float(__ushort_as_half((unsigned short)(r >> 17)));
}

__global__ void k_gather(const uint4* __restrict__ hprev, uint4* __restrict__ hcur) {
    int gid = blockIdx.x * blockDim.x + threadIdx.x;
    int n = gid >> 3;
    int q = gid & 7;
    if (n >= NN) return;
    int2 ri = g_rowinfo[n];
    int e = ri.x;
    int end = e + ri.y;
    float acc[8] = {0.f, 0.f, 0.f, 0.f, 0.f, 0.f, 0.f, 0.f};
    for (; e + 8 <= end; e += 8) {
        unsigned r[8];
        #pragma unroll
        for (int j = 0; j < 8; j++) r[j] = g_csr[e + j];
        uint4 v[8];
        #pragma unroll
        for (int j = 0; j < 8; j++) v[j] = hprev[(int)(r[j] & 0x1FFFFu) * 8 + q];
        #pragma unroll
        for (int j = 0; j < 8; j++)
            acc_half8(acc, csr_w(r[j]), v[j]);
    }
    for (; e + 4 <= end; e += 4) {
        unsigned r[4];
        #pragma unroll
        for (int j = 0; j < 4; j++) r[j] = g_csr[e + j];
        uint4 v[4];
        #pragma unroll
        for (int j = 0; j < 4; j++) v[j] = hprev[(int)(r[j] & 0x1FFFFu) * 8 + q];
        #pragma unroll
        for (int j = 0; j < 4; j++)
            acc_half8(acc, csr_w(r[j]), v[j]);
    }
    for (; e < end; e++) {
        unsigned r0 = g_csr[e];
        uint4 v0 = hprev[(int)(r0 & 0x1FFFFu) * 8 + q];
        acc_half8(acc, csr_w(r0), v0);
    }
    uint4 o;
    __half2 o0 = __float22half2_rn(make_float2(acc[0], acc[1]));
    __half2 o1 = __float22half2_rn(make_float2(acc[2], acc[3]));
    __half2 o2 = __float22half2_rn(make_float2(acc[4], acc[5]));
    __half2 o3 = __float22half2_rn(make_float2(acc[6], acc[7]));
    o.x = *reinterpret_cast<unsigned*>(&o0);
    o.y = *reinterpret_cast<unsigned*>(&o1);
    o.z = *reinterpret_cast<unsigned*>(&o2);
    o.w = *reinterpret_cast<unsigned*>(&o3);
    hcur[n * 8 + q] = o;
}

// ---------------- tensor-core 4-way matmul: out = b + sum_m Xm @ Wm -------------
#define WT_STRIDE 72
__global__ void __launch_bounds__(256) k_mat4_mma(
        const __half* __restrict__ X0, const __half* __restrict__ X1,
        const __half* __restrict__ X2, const __half* __restrict__ X3,
        const float* __restrict__ bias, float* __restrict__ out) {
    __shared__ __half sW[4 * 64 * WT_STRIDE];   // 36864 B
    int tid = threadIdx.x;

    {
        const uint4* srcp = (const uint4*)g_whT;
        uint4* dstp = (uint4*)sW;
        #pragma unroll
        for (int i = 0; i < 9; i++) dstp[tid + i * 256] = srcp[tid + i * 256];
    }
    __syncthreads();

    int warp = tid >> 5;
    int lane = tid & 31;
    int rowbase = blockIdx.x * 128 + warp * 16;
    int r1 = rowbase + (lane >> 2);
    int r2 = r1 + 8;
    int qk = (lane & 3) * 2;
    int lr1 = min(r1, NN - 1);
    int lr2 = min(r2, NN - 1);

    unsigned swbase = (unsigned)__cvta_generic_to_shared(sW);
    unsigned rowptr = swbase + (lane & 7) * 144 + ((lane >> 3) & 1) * 16
                    + ((lane >> 4) & 1) * 1152;

    float c[8][4];
    #pragma unroll
    for (int nt = 0; nt < 8; nt++) {
        float2 bv = *reinterpret_cast<const float2*>(&bias[nt * 8 + qk]);
        c[nt][0] = bv.x; c[nt][1] = bv.y; c[nt][2] = bv.x; c[nt][3] = bv.y;
    }

    const __half* Xs[4] = {X0, X1, X2, X3};
    #pragma unroll
    for (int m = 0; m < 4; m++) {
        const __half* Xm = Xs[m];
        unsigned mbase = rowptr + m * 9216;
        #pragma unroll
        for (int ks = 0; ks < 4; ks++) {
            unsigned a0 = *reinterpret_cast<const unsigned*>(&Xm[lr1 * 64 + ks * 16 + qk]);
            unsigned a1 = *reinterpret_cast<const unsigned*>(&Xm[lr2 * 64 + ks * 16 + qk]);
            unsigned a2 = *reinterpret_cast<const unsigned*>(&Xm[lr1 * 64 + ks * 16 + qk + 8]);
            unsigned a3 = *reinterpret_cast<const unsigned*>(&Xm[lr2 * 64 + ks * 16 + qk + 8]);
            #pragma unroll
            for (int np = 0; np < 4; np++) {
                unsigned b0, b1, b2, b3;
                unsigned addr = mbase + np * 2304 + ks * 32;
                asm volatile(
                    "ldmatrix.sync.aligned.m8n8.x4.shared.b16 {%0,%1,%2,%3}, [%4];"
                    : "=r"(b0), "=r"(b1), "=r"(b2), "=r"(b3) : "r"(addr));
                int nt = np * 2;
                asm volatile(
                    "mma.sync.aligned.m16n8k16.row.col.f32.f16.f16.f32 "
                    "{%0,%1,%2,%3}, {%4,%5,%6,%7}, {%8,%9}, {%0,%1,%2,%3};"
                    : "+f"(c[nt][0]), "+f"(c[nt][1]), "+f"(c[nt][2]), "+f"(c[nt][3])
                    : "r"(a0), "r"(a1), "r"(a2), "r"(a3), "r"(b0), "r"(b1));
                asm volatile(
                    "mma.sync.aligned.m16n8k16.row.col.f32.f16.f16.f32 "
                    "{%0,%1,%2,%3}, {%4,%5,%6,%7}, {%8,%9}, {%0,%1,%2,%3};"
                    : "+f"(c[nt+1][0]), "+f"(c[nt+1][1]), "+f"(c[nt+1][2]), "+f"(c[nt+1][3])
                    : "r"(a0), "r"(a1), "r"(a2), "r"(a3), "r"(b2), "r"(b3));
            }
        }
    }

    bool s1 = (r1 < NN), s2 = (r2 < NN);
    #pragma unroll
    for (int nt = 0; nt < 8; nt++) {
        if (s1) *reinterpret_cast<float2*>(&out[r1 * 64 + nt * 8 + qk]) =
            make_float2(c[nt][0], c[nt][1]);
        if (s2) *reinterpret_cast<float2*>(&out[r2 * 64 + nt * 8 + qk]) =
            make_float2(c[nt][2], c[nt][3]);
    }
}

// ---------------- GraphNorm stats: 64 rows per block (4x parallelism) -----------
#define SROWS 64
__global__ void k_stats(const float* __restrict__ out, const int* __restrict__ batch) {
    int f = threadIdx.x & 63;
    int rg = threadIdx.x >> 6;
    int row0 = blockIdx.x * SROWS;
    int rend = min(row0 + SROWS, NN);
    float s = 0.f, sq = 0.f, c = 0.f;
    int curg = -1;
    for (int r = row0 + rg; r < rend; r += 4) {
        int g = batch[r];
        if (g != curg) {
            if (curg >= 0) {
                atomicAdd(&g_sum[curg * 64 + f], s);
                atomicAdd(&g_sumsq[curg * 64 + f], sq);
                if (f == 0) atomicAdd(&g_cnt[curg], c);
            }
            curg = g; s = 0.f; sq = 0.f; c = 0.f;
        }
        float v = out[r * 64 + f];
        s += v; sq += v * v; c += 1.f;
    }
    if (curg >= 0) {
        atomicAdd(&g_sum[curg * 64 + f], s);
        atomicAdd(&g_sumsq[curg * 64 + f], sq);
        if (f == 0) atomicAdd(&g_cnt[curg], c);
    }
}

// ---------------- per-(g,f) scale/shift ------------------------------------------
__global__ void k_prep(const float* __restrict__ gn_w, const float* __restrict__ gn_b,
                       const float* __restrict__ gn_ms) {
    int idx = blockIdx.x * blockDim.x + threadIdx.x;
    if (idx >= G * F) return;
    int g = idx >> 6, f = idx & 63;
    float cnt = fmaxf(g_cnt[g], 1.f);
    float m = g_sum[idx] / cnt;
    float ms = m * gn_ms[f];
    float var = g_sumsq[idx] / cnt - ms * (2.f * m - ms);
    var = fmaxf(var, 0.f);
    float sc = gn_w[f] * rsqrtf(var + EPS);
    g_scale[idx] = sc;
    g_shift[idx] = gn_b[f] - ms * sc;
}

// ---------------- normalize + residual + relu + pooling: 64 rows per block ------
__global__ void k_final(const float* __restrict__ out, const float* __restrict__ x,
                        const int* __restrict__ batch, float* __restrict__ demb) {
    int f = threadIdx.x & 63;
    int rg = threadIdx.x >> 6;
    int row0 = blockIdx.x * SROWS;
    int rend = min(row0 + SROWS, NN);
    float s = 0.f, mx = 0.f;
    int curg = -1;
    float sc = 0.f, sh = 0.f;
    for (int r = row0 + rg; r < rend; r += 4) {
        int g = batch[r];
        if (g != curg) {
            if (curg >= 0) {
                atomicAdd(&g_psum[curg * 64 + f], s);
                atomicMax(reinterpret_cast<int*>(&g_pmax[curg * 64 + f]), __float_as_int(mx));
            }
            curg = g; s = 0.f; mx = 0.f;
            sc = g_scale[g * 64 + f];
            sh = g_shift[g * 64 + f];
        }
        float v = out[r * 64 + f] * sc + sh + x[r * 64 + f];
        v = fmaxf(v, 0.f);
        demb[r * 64 + f] = v;
        s += v;
        mx = fmaxf(mx, v);
    }
    if (curg >= 0) {
        atomicAdd(&g_psum[curg * 64 + f], s);
        atomicMax(reinterpret_cast<int*>(&g_pmax[curg * 64 + f]), __float_as_int(mx));
    }
}

// ---------------- flat output: [G, 2F] ---------------------------------------------
__global__ void k_flat(float* __restrict__ flat) {
    int idx = blockIdx.x * blockDim.x + threadIdx.x;
    if (idx >= G * 2 * F) return;
    int g = idx >> 7, j = idx & 127;
    float cnt = fmaxf(g_cnt[g], 1.f);
    flat[idx] = (j < 64) ? (g_psum[g * 64 + j] / cnt) : g_pmax[g * 64 + (j - 64)];
}

// ---------------- launch -------------------------------------------------------------
extern "C" void kernel_launch(void* const* d_in, const int* in_sizes, int n_in,
                              void* d_out, int out_size) {
    const float* x     = (const float*)d_in[0];
    const int*   ei    = (const int*)d_in[1];
    const int*   batch = (const int*)d_in[2];
    const float* ew    = (const float*)d_in[3];
    const float* W     = (const float*)d_in[4];
    const float* bias  = (const float*)d_in[5];
    const float* gn_w  = (const float*)d_in[6];
    const float* gn_b  = (const float*)d_in[7];
    const float* gn_ms = (const float*)d_in[8];

    float* demb = (float*)d_out;
    float* flat = (float*)d_out + (size_t)NN * F;

    const int* src = ei;
    const int* dst = ei + NE;

    __half *pxh, *ph1, *ph2, *ph3;
    float *pout;
    cudaGetSymbolAddress((void**)&pxh, g_xh);
    cudaGetSymbolAddress((void**)&ph1, g_h1);
    cudaGetSymbolAddress((void**)&ph2, g_h2);
    cudaGetSymbolAddress((void**)&ph3, g_h3);
    cudaGetSymbolAddress((void**)&pout, g_out);

    k_zero<<<256, 256>>>();
    k_deg<<<(NE + 255) / 256, 256>>>(dst, ew, (const float2*)x, W);
    k_offsets<<<(NN + 255) / 256, 256>>>();
    k_scatter<<<(NE + 255) / 256, 256>>>(src, dst, ew);

    int gat_blocks = (NN * 8 + 255) / 256;
    k_gather<<<gat_blocks, 256>>>((const uint4*)pxh, (uint4*)ph1);
    k_gather<<<gat_blocks, 256>>>((const uint4*)ph1, (uint4*)ph2);
    k_gather<<<gat_blocks, 256>>>((const uint4*)ph2, (uint4*)ph3);

    int mat_blocks = (NN + 127) / 128;
    k_mat4_mma<<<mat_blocks, 256>>>(pxh, ph1, ph2, ph3, bias, pout);

    int row_blocks = (NN + SROWS - 1) / SROWS;
    k_stats<<<row_blocks, 256>>>(pout, batch);
    k_prep<<<(G * F + 255) / 256, 256>>>(gn_w, gn_b, gn_ms);
    k_final<<<row_blocks, 256>>>(pout, x, batch, demb);
    k_flat<<<(G * 2 * F + 255) / 256, 256>>>(flat);
}

// round 13
// speedup vs baseline: 1.2476x; 1.0245x over previous
#include <cuda_runtime.h>
#include <cuda_fp16.h>

#define NN 100000
#define NE 1600000
#define F 64
#define G 64
#define EPS 1e-5f

// ---------------- scratch (device globals) ----------------------------------
__device__ float2 g_degcnt[NN];            // .x = weighted deg, .y = count
__device__ float g_dis[NN];
__device__ int2  g_rowinfo[NN];            // {start, count}
__device__ int   g_rank[NE];               // per-edge slot within its dst row
__device__ int   g_total;
__device__ unsigned g_csr[NE];             // bits[31:17] = fp16 (dis[src]*w), [16:0] = src
__device__ __half g_xh[NN * F];            // x in fp16
__device__ __half g_h1[NN * F];
__device__ __half g_h2[NN * F];
__device__ __half g_h3[NN * F];
__device__ __half g_whT[4 * 64 * 72];      // W fp16, n-major [m][n][k], stride 72
__device__ float g_out[NN * F];
__device__ float g_sum[G * F];
__device__ float g_sumsq[G * F];
__device__ float g_cnt[G];
__device__ float g_scale[G * F];
__device__ float g_shift[G * F];
__device__ float g_psum[G * F];
__device__ float g_pmax[G * F];

// ---------------- tiny zero: only what k_deg needs ----------------------------
__global__ void k_zero() {
    int i = blockIdx.x * blockDim.x + threadIdx.x;
    int st = gridDim.x * blockDim.x;
    for (int j = i; j < NN; j += st) g_degcnt[j] = make_float2(0.f, 0.f);
    if (i == 0) g_total = 0;
}

// ---------------- degree+rank, fused with conversions & small zeroing ---------
__global__ void k_deg(const int* __restrict__ dst, const float* __restrict__ w,
                      const float2* __restrict__ x, const float* __restrict__ W) {
    int i = blockIdx.x * blockDim.x + threadIdx.x;
    int st = gridDim.x * blockDim.x;                // 1.6M threads
    if (i < NE) {
        float2 old = atomicAdd(&g_degcnt[dst[i]], make_float2(w[i], 1.f));
        g_rank[i] = (int)old.y;
    }
    // independent streaming work rides under the atomic latency:
    for (int j = i; j < NN * F / 2; j += st)
        reinterpret_cast<__half2*>(g_xh)[j] = __float22half2_rn(x[j]);
    if (i < G * F) {
        g_sum[i] = 0.f; g_sumsq[i] = 0.f; g_psum[i] = 0.f; g_pmax[i] = 0.f;
        if (i < G) g_cnt[i] = 0.f;
    }
    if (i < 4 * 64 * 64) {
        int m = i >> 12;
        int k = (i >> 6) & 63;
        int n = i & 63;
        g_whT[m * 64 * 72 + n * 72 + k] = __float2half_rn(W[i]);
    }
}

// ---------------- offsets: block scan + global cursor (order-free CSR) --------
__global__ void k_offsets() {
    __shared__ int s[256];
    __shared__ int sbase;
    int tid = threadIdx.x;
    int i = blockIdx.x * 256 + tid;
    float2 dc = (i < NN) ? g_degcnt[i] : make_float2(0.f, 0.f);
    int c = (int)dc.y;
    s[tid] = c;
    __syncthreads();
    #pragma unroll
    for (int off = 1; off < 256; off <<= 1) {
        int t = (tid >= off) ? s[tid - off] : 0;
        __syncthreads();
        s[tid] += t;
        __syncthreads();
    }
    if (tid == 255) sbase = atomicAdd(&g_total, s[255]);
    __syncthreads();
    if (i < NN) {
        int start = sbase + s[tid] - c;
        g_rowinfo[i] = make_int2(start, c);
        g_dis[i] = dc.x > 0.f ? rsqrtf(dc.x) : 0.f;
    }
}

// ---------------- scatter: store dis[src]*w only (dis[dst] hoisted to gather) --
__global__ void k_scatter(const int* __restrict__ src, const int* __restrict__ dst,
                          const float* __restrict__ w) {
    int e = blockIdx.x * blockDim.x + threadIdx.x;
    if (e >= NE) return;
    int s = src[e];
    int d = dst[e];
    float nw = g_dis[s] * w[e];                      // >= 0, sign bit of fp16 is 0
    unsigned short hb = __half_as_ushort(__float2half_rn(nw));
    int p = g_rowinfo[d].x + g_rank[e];
    g_csr[p] = ((unsigned)hb << 17) | (unsigned)s;
}

// ---------------- gather hop (fp16 rows): 8 lanes/node, LDG.128, unroll 8 -----
// hcur[n] = dis[n] * sum_e (dis[src]*w)_e * hprev[src_e]
__device__ __forceinline__ void acc_half8(float* acc, float w, uint4 v) {
    float2 f0 = __half22float2(*reinterpret_cast<__half2*>(&v.x));
    float2 f1 = __half22float2(*reinterpret_cast<__half2*>(&v.y));
    float2 f2 = __half22float2(*reinterpret_cast<__half2*>(&v.z));
    float2 f3 = __half22float2(*reinterpret_cast<__half2*>(&v.w));
    acc[0] = fmaf(w, f0.x, acc[0]); acc[1] = fmaf(w, f0.y, acc[1]);
    acc[2] = fmaf(w, f1.x, acc[2]); acc[3] = fmaf(w, f1.y, acc[3]);
    acc[4] = fmaf(w, f2.x, acc[4]); acc[5] = fmaf(w, f2.y, acc[5]);
    acc[6] = fmaf(w, f3.x, acc[6]); acc[7] = fmaf(w, f3.y, acc[7]);
}
__device__ __forceinline__ float csr_w(unsigned r) {
    return __half2float(__ushort_as_half((unsigned short)(r >> 17)));
}

__global__ void k_gather(const uint4* __restrict__ hprev, uint4* __restrict__ hcur) {
    int gid = blockIdx.x * blockDim.x + threadIdx.x;
    int n = gid >> 3;
    int q = gid & 7;
    if (n >= NN) return;
    int2 ri = g_rowinfo[n];
    int e = ri.x;
    int end = e + ri.y;
    float acc[8] = {0.f, 0.f, 0.f, 0.f, 0.f, 0.f, 0.f, 0.f};
    for (; e + 8 <= end; e += 8) {
        unsigned r[8];
        #pragma unroll
        for (int j = 0; j < 8; j++) r[j] = g_csr[e + j];
        uint4 v[8];
        #pragma unroll
        for (int j = 0; j < 8; j++) v[j] = hprev[(int)(r[j] & 0x1FFFFu) * 8 + q];
        #pragma unroll
        for (int j = 0; j < 8; j++)
            acc_half8(acc, csr_w(r[j]), v[j]);
    }
    for (; e + 4 <= end; e += 4) {
        unsigned r[4];
        #pragma unroll
        for (int j = 0; j < 4; j++) r[j] = g_csr[e + j];
        uint4 v[4];
        #pragma unroll
        for (int j = 0; j < 4; j++) v[j] = hprev[(int)(r[j] & 0x1FFFFu) * 8 + q];
        #pragma unroll
        for (int j = 0; j < 4; j++)
            acc_half8(acc, csr_w(r[j]), v[j]);
    }
    for (; e < end; e++) {
        unsigned r0 = g_csr[e];
        uint4 v0 = hprev[(int)(r0 & 0x1FFFFu) * 8 + q];
        acc_half8(acc, csr_w(r0), v0);
    }
    float dn = g_dis[n];
    uint4 o;
    __half2 o0 = __floats2half2_rn(acc[0] * dn, acc[1] * dn);
    __half2 o1 = __floats2half2_rn(acc[2] * dn, acc[3] * dn);
    __half2 o2 = __floats2half2_rn(acc[4] * dn, acc[5] * dn);
    __half2 o3 = __floats2half2_rn(acc[6] * dn, acc[7] * dn);
    o.x = *reinterpret_cast<unsigned*>(&o0);
    o.y = *reinterpret_cast<unsigned*>(&o1);
    o.z = *reinterpret_cast<unsigned*>(&o2);
    o.w = *reinterpret_cast<unsigned*>(&o3);
    hcur[n * 8 + q] = o;
}

// ---------------- tensor-core 4-way matmul: out = b + sum_m Xm @ Wm -------------
#define WT_STRIDE 72
__global__ void __launch_bounds__(256) k_mat4_mma(
        const __half* __restrict__ X0, const __half* __restrict__ X1,
        const __half* __restrict__ X2, const __half* __restrict__ X3,
        const float* __restrict__ bias, float* __restrict__ out) {
    __shared__ __half sW[4 * 64 * WT_STRIDE];   // 36864 B
    int tid = threadIdx.x;

    {
        const uint4* srcp = (const uint4*)g_whT;
        uint4* dstp = (uint4*)sW;
        #pragma unroll
        for (int i = 0; i < 9; i++) dstp[tid + i * 256] = srcp[tid + i * 256];
    }
    __syncthreads();

    int warp = tid >> 5;
    int lane = tid & 31;
    int rowbase = blockIdx.x * 128 + warp * 16;
    int r1 = rowbase + (lane >> 2);
    int r2 = r1 + 8;
    int qk = (lane & 3) * 2;
    int lr1 = min(r1, NN - 1);
    int lr2 = min(r2, NN - 1);

    unsigned swbase = (unsigned)__cvta_generic_to_shared(sW);
    unsigned rowptr = swbase + (lane & 7) * 144 + ((lane >> 3) & 1) * 16
                    + ((lane >> 4) & 1) * 1152;

    float c[8][4];
    #pragma unroll
    for (int nt = 0; nt < 8; nt++) {
        float2 bv = *reinterpret_cast<const float2*>(&bias[nt * 8 + qk]);
        c[nt][0] = bv.x; c[nt][1] = bv.y; c[nt][2] = bv.x; c[nt][3] = bv.y;
    }

    const __half* Xs[4] = {X0, X1, X2, X3};
    #pragma unroll
    for (int m = 0; m < 4; m++) {
        const __half* Xm = Xs[m];
        unsigned mbase = rowptr + m * 9216;
        #pragma unroll
        for (int ks = 0; ks < 4; ks++) {
            unsigned a0 = *reinterpret_cast<const unsigned*>(&Xm[lr1 * 64 + ks * 16 + qk]);
            unsigned a1 = *reinterpret_cast<const unsigned*>(&Xm[lr2 * 64 + ks * 16 + qk]);
            unsigned a2 = *reinterpret_cast<const unsigned*>(&Xm[lr1 * 64 + ks * 16 + qk + 8]);
            unsigned a3 = *reinterpret_cast<const unsigned*>(&Xm[lr2 * 64 + ks * 16 + qk + 8]);
            #pragma unroll
            for (int np = 0; np < 4; np++) {
                unsigned b0, b1, b2, b3;
                unsigned addr = mbase + np * 2304 + ks * 32;
                asm volatile(
                    "ldmatrix.sync.aligned.m8n8.x4.shared.b16 {%0,%1,%2,%3}, [%4];"
                    : "=r"(b0), "=r"(b1), "=r"(b2), "=r"(b3) : "r"(addr));
                int nt = np * 2;
                asm volatile(
                    "mma.sync.aligned.m16n8k16.row.col.f32.f16.f16.f32 "
                    "{%0,%1,%2,%3}, {%4,%5,%6,%7}, {%8,%9}, {%0,%1,%2,%3};"
                    : "+f"(c[nt][0]), "+f"(c[nt][1]), "+f"(c[nt][2]), "+f"(c[nt][3])
                    : "r"(a0), "r"(a1), "r"(a2), "r"(a3), "r"(b0), "r"(b1));
                asm volatile(
                    "mma.sync.aligned.m16n8k16.row.col.f32.f16.f16.f32 "
                    "{%0,%1,%2,%3}, {%4,%5,%6,%7}, {%8,%9}, {%0,%1,%2,%3};"
                    : "+f"(c[nt+1][0]), "+f"(c[nt+1][1]), "+f"(c[nt+1][2]), "+f"(c[nt+1][3])
                    : "r"(a0), "r"(a1), "r"(a2), "r"(a3), "r"(b2), "r"(b3));
            }
        }
    }

    bool s1 = (r1 < NN), s2 = (r2 < NN);
    #pragma unroll
    for (int nt = 0; nt < 8; nt++) {
        if (s1) *reinterpret_cast<float2*>(&out[r1 * 64 + nt * 8 + qk]) =
            make_float2(c[nt][0], c[nt][1]);
        if (s2) *reinterpret_cast<float2*>(&out[r2 * 64 + nt * 8 + qk]) =
            make_float2(c[nt][2], c[nt][3]);
    }
}

// ---------------- GraphNorm stats: 64 rows per block -----------------------------
#define SROWS 64
__global__ void k_stats(const float* __restrict__ out, const int* __restrict__ batch) {
    int f = threadIdx.x & 63;
    int rg = threadIdx.x >> 6;
    int row0 = blockIdx.x * SROWS;
    int rend = min(row0 + SROWS, NN);
    float s = 0.f, sq = 0.f, c = 0.f;
    int curg = -1;
    for (int r = row0 + rg; r < rend; r += 4) {
        int g = batch[r];
        if (g != curg) {
            if (curg >= 0) {
                atomicAdd(&g_sum[curg * 64 + f], s);
                atomicAdd(&g_sumsq[curg * 64 + f], sq);
                if (f == 0) atomicAdd(&g_cnt[curg], c);
            }
            curg = g; s = 0.f; sq = 0.f; c = 0.f;
        }
        float v = out[r * 64 + f];
        s += v; sq += v * v; c += 1.f;
    }
    if (curg >= 0) {
        atomicAdd(&g_sum[curg * 64 + f], s);
        atomicAdd(&g_sumsq[curg * 64 + f], sq);
        if (f == 0) atomicAdd(&g_cnt[curg], c);
    }
}

// ---------------- per-(g,f) scale/shift ------------------------------------------
__global__ void k_prep(const float* __restrict__ gn_w, const float* __restrict__ gn_b,
                       const float* __restrict__ gn_ms) {
    int idx = blockIdx.x * blockDim.x + threadIdx.x;
    if (idx >= G * F) return;
    int g = idx >> 6, f = idx & 63;
    float cnt = fmaxf(g_cnt[g], 1.f);
    float m = g_sum[idx] / cnt;
    float ms = m * gn_ms[f];
    float var = g_sumsq[idx] / cnt - ms * (2.f * m - ms);
    var = fmaxf(var, 0.f);
    float sc = gn_w[f] * rsqrtf(var + EPS);
    g_scale[idx] = sc;
    g_shift[idx] = gn_b[f] - ms * sc;
}

// ---------------- normalize + residual + relu + pooling: 64 rows per block ------
__global__ void k_final(const float* __restrict__ out, const float* __restrict__ x,
                        const int* __restrict__ batch, float* __restrict__ demb) {
    int f = threadIdx.x & 63;
    int rg = threadIdx.x >> 6;
    int row0 = blockIdx.x * SROWS;
    int rend = min(row0 + SROWS, NN);
    float s = 0.f, mx = 0.f;
    int curg = -1;
    float sc = 0.f, sh = 0.f;
    for (int r = row0 + rg; r < rend; r += 4) {
        int g = batch[r];
        if (g != curg) {
            if (curg >= 0) {
                atomicAdd(&g_psum[curg * 64 + f], s);
                atomicMax(reinterpret_cast<int*>(&g_pmax[curg * 64 + f]), __float_as_int(mx));
            }
            curg = g; s = 0.f; mx = 0.f;
            sc = g_scale[g * 64 + f];
            sh = g_shift[g * 64 + f];
        }
        float v = out[r * 64 + f] * sc + sh + x[r * 64 + f];
        v = fmaxf(v, 0.f);
        demb[r * 64 + f] = v;
        s += v;
        mx = fmaxf(mx, v);
    }
    if (curg >= 0) {
        atomicAdd(&g_psum[curg * 64 + f], s);
        atomicMax(reinterpret_cast<int*>(&g_pmax[curg * 64 + f]), __float_as_int(mx));
    }
}

// ---------------- flat output: [G, 2F] ---------------------------------------------
__global__ void k_flat(float* __restrict__ flat) {
    int idx = blockIdx.x * blockDim.x + threadIdx.x;
    if (idx >= G * 2 * F) return;
    int g = idx >> 7, j = idx & 127;
    float cnt = fmaxf(g_cnt[g], 1.f);
    flat[idx] = (j < 64) ? (g_psum[g * 64 + j] / cnt) : g_pmax[g * 64 + (j - 64)];
}

// ---------------- launch -------------------------------------------------------------
extern "C" void kernel_launch(void* const* d_in, const int* in_sizes, int n_in,
                              void* d_out, int out_size) {
    const float* x     = (const float*)d_in[0];
    const int*   ei    = (const int*)d_in[1];
    const int*   batch = (const int*)d_in[2];
    const float* ew    = (const float*)d_in[3];
    const float* W     = (const float*)d_in[4];
    const float* bias  = (const float*)d_in[5];
    const float* gn_w  = (const float*)d_in[6];
    const float* gn_b  = (const float*)d_in[7];
    const float* gn_ms = (const float*)d_in[8];

    float* demb = (float*)d_out;
    float* flat = (float*)d_out + (size_t)NN * F;

    const int* src = ei;
    const int* dst = ei + NE;

    __half *pxh, *ph1, *ph2, *ph3;
    float *pout;
    cudaGetSymbolAddress((void**)&pxh, g_xh);
    cudaGetSymbolAddress((void**)&ph1, g_h1);
    cudaGetSymbolAddress((void**)&ph2, g_h2);
    cudaGetSymbolAddress((void**)&ph3, g_h3);
    cudaGetSymbolAddress((void**)&pout, g_out);

    k_zero<<<256, 256>>>();
    k_deg<<<(NE + 255) / 256, 256>>>(dst, ew, (const float2*)x, W);
    k_offsets<<<(NN + 255) / 256, 256>>>();
    k_scatter<<<(NE + 255) / 256, 256>>>(src, dst, ew);

    int gat_blocks = (NN * 8 + 255) / 256;
    k_gather<<<gat_blocks, 256>>>((const uint4*)pxh, (uint4*)ph1);
    k_gather<<<gat_blocks, 256>>>((const uint4*)ph1, (uint4*)ph2);
    k_gather<<<gat_blocks, 256>>>((const uint4*)ph2, (uint4*)ph3);

    int mat_blocks = (NN + 127) / 128;
    k_mat4_mma<<<mat_blocks, 256>>>(pxh, ph1, ph2, ph3, bias, pout);

    int row_blocks = (NN + SROWS - 1) / SROWS;
    k_stats<<<row_blocks, 256>>>(pout, batch);
    k_prep<<<(G * F + 255) / 256, 256>>>(gn_w, gn_b, gn_ms);
    k_final<<<row_blocks, 256>>>(pout, x, batch, demb);
    k_flat<<<(G * 2 * F + 255) / 256, 256>>>(flat);
}

// round 14
// speedup vs baseline: 1.2739x; 1.0211x over previous
#include <cuda_runtime.h>
#include <cuda_fp16.h>

#define NN 100000
#define NE 1600000
#define F 64
#define G 64
#define EPS 1e-5f
#define CSR_CAP (NE + 7 * NN + 16)   // padded rows: worst case +7 per node

// ---------------- scratch (device globals) ----------------------------------
__device__ float2 g_degcnt[NN];            // .x = weighted deg, .y = count
__device__ float g_dis[NN];
__device__ int2  g_rowinfo[NN];            // {start (8-aligned), padded count}
__device__ int   g_rank[NE];               // per-edge slot within its dst row
__device__ int   g_total;
__device__ __align__(16) unsigned g_csr[CSR_CAP]; // [31:17]=fp16(dis[src]*w), [16:0]=src
__device__ __half g_xh[NN * F];            // x in fp16
__device__ __half g_h1[NN * F];
__device__ __half g_h2[NN * F];
__device__ __half g_h3[NN * F];
__device__ __half g_whT[4 * 64 * 72];      // W fp16, n-major [m][n][k], stride 72
__device__ float g_out[NN * F];
__device__ float g_sum[G * F];
__device__ float g_sumsq[G * F];
__device__ float g_cnt[G];
__device__ float g_scale[G * F];
__device__ float g_shift[G * F];
__device__ float g_psum[G * F];
__device__ float g_pmax[G * F];

// ---------------- tiny zero: only what k_deg needs ----------------------------
__global__ void k_zero() {
    int i = blockIdx.x * blockDim.x + threadIdx.x;
    int st = gridDim.x * blockDim.x;
    for (int j = i; j < NN; j += st) g_degcnt[j] = make_float2(0.f, 0.f);
    if (i == 0) g_total = 0;
}

// ---------------- degree+rank, fused with conversions & small zeroing ---------
__global__ void k_deg(const int* __restrict__ dst, const float* __restrict__ w,
                      const float2* __restrict__ x, const float* __restrict__ W) {
    int i = blockIdx.x * blockDim.x + threadIdx.x;
    int st = gridDim.x * blockDim.x;                // 1.6M threads
    if (i < NE) {
        float2 old = atomicAdd(&g_degcnt[dst[i]], make_float2(w[i], 1.f));
        g_rank[i] = (int)old.y;
    }
    // independent streaming work rides under the atomic latency:
    for (int j = i; j < NN * F / 2; j += st)
        reinterpret_cast<__half2*>(g_xh)[j] = __float22half2_rn(x[j]);
    if (i < G * F) {
        g_sum[i] = 0.f; g_sumsq[i] = 0.f; g_psum[i] = 0.f; g_pmax[i] = 0.f;
        if (i < G) g_cnt[i] = 0.f;
    }
    if (i < 4 * 64 * 64) {
        int m = i >> 12;
        int k = (i >> 6) & 63;
        int n = i & 63;
        g_whT[m * 64 * 72 + n * 72 + k] = __float2half_rn(W[i]);
    }
}

// ---------------- offsets: scan of PADDED counts + zero-fill padding ----------
__global__ void k_offsets() {
    __shared__ int s[256];
    __shared__ int sbase;
    int tid = threadIdx.x;
    int i = blockIdx.x * 256 + tid;
    float2 dc = (i < NN) ? g_degcnt[i] : make_float2(0.f, 0.f);
    int c = (int)dc.y;
    int pc = (c + 7) & ~7;                 // padded to multiple of 8
    s[tid] = pc;
    __syncthreads();
    #pragma unroll
    for (int off = 1; off < 256; off <<= 1) {
        int t = (tid >= off) ? s[tid - off] : 0;
        __syncthreads();
        s[tid] += t;
        __syncthreads();
    }
    if (tid == 255) sbase = atomicAdd(&g_total, s[255]);
    __syncthreads();
    if (i < NN) {
        int start = sbase + s[tid] - pc;   // multiple of 8
        g_rowinfo[i] = make_int2(start, pc);
        g_dis[i] = dc.x > 0.f ? rsqrtf(dc.x) : 0.f;
        // zero-fill pad entries (w=0, src=0 -> contributes 0)
        for (int p = start + c; p < start + pc; p++) g_csr[p] = 0u;
    }
}

// ---------------- scatter: store dis[src]*w (dis[dst] hoisted to gather) -------
__global__ void k_scatter(const int* __restrict__ src, const int* __restrict__ dst,
                          const float* __restrict__ w) {
    int e = blockIdx.x * blockDim.x + threadIdx.x;
    if (e >= NE) return;
    int s = src[e];
    int d = dst[e];
    float nw = g_dis[s] * w[e];                      // >= 0, sign bit of fp16 is 0
    unsigned short hb = __half_as_ushort(__float2half_rn(nw));
    int p = g_rowinfo[d].x + g_rank[e];
    g_csr[p] = ((unsigned)hb << 17) | (unsigned)s;
}

// ---------------- gather hop: 8 lanes/node, padded rows -> no tails ------------
// hcur[n] = dis[n] * sum_e (dis[src]*w)_e * hprev[src_e]
__device__ __forceinline__ void acc_half8(float* acc, float w, uint4 v) {
    float2 f0 = __half22float2(*reinterpret_cast<__half2*>(&v.x));
    float2 f1 = __half22float2(*reinterpret_cast<__half2*>(&v.y));
    float2 f2 = __half22float2(*reinterpret_cast<__half2*>(&v.z));
    float2 f3 = __half22float2(*reinterpret_cast<__half2*>(&v.w));
    acc[0] = fmaf(w, f0.x, acc[0]); acc[1] = fmaf(w, f0.y, acc[1]);
    acc[2] = fmaf(w, f1.x, acc[2]); acc[3] = fmaf(w, f1.y, acc[3]);
    acc[4] = fmaf(w, f2.x, acc[4]); acc[5] = fmaf(w, f2.y, acc[5]);
    acc[6] = fmaf(w, f3.x, acc[6]); acc[7] = fmaf(w, f3.y, acc[7]);
}
__device__ __forceinline__ float csr_w(unsigned r) {
    return __half2float(__ushort_as_half((unsigned short)(r >> 17)));
}

__global__ void k_gather(const uint4* __restrict__ hprev, uint4* __restrict__ hcur) {
    int gid = blockIdx.x * blockDim.x + threadIdx.x;
    int n = gid >> 3;
    int q = gid & 7;
    if (n >= NN) return;
    int2 ri = g_rowinfo[n];
    int e = ri.x;                           // multiple of 8 -> 32B aligned
    int end = e + ri.y;                     // padded count, multiple of 8
    float acc[8] = {0.f, 0.f, 0.f, 0.f, 0.f, 0.f, 0.f, 0.f};
    for (; e < end; e += 8) {
        uint4 ra = *reinterpret_cast<const uint4*>(&g_csr[e]);
        uint4 rb = *reinterpret_cast<const uint4*>(&g_csr[e + 4]);
        unsigned r[8] = {ra.x, ra.y, ra.z, ra.w, rb.x, rb.y, rb.z, rb.w};
        uint4 v[8];
        #pragma unroll
        for (int j = 0; j < 8; j++) v[j] = hprev[(int)(r[j] & 0x1FFFFu) * 8 + q];
        #pragma unroll
        for (int j = 0; j < 8; j++)
            acc_half8(acc, csr_w(r[j]), v[j]);
    }
    float dn = g_dis[n];
    uint4 o;
    __half2 o0 = __floats2half2_rn(acc[0] * dn, acc[1] * dn);
    __half2 o1 = __floats2half2_rn(acc[2] * dn, acc[3] * dn);
    __half2 o2 = __floats2half2_rn(acc[4] * dn, acc[5] * dn);
    __half2 o3 = __floats2half2_rn(acc[6] * dn, acc[7] * dn);
    o.x = *reinterpret_cast<unsigned*>(&o0);
    o.y = *reinterpret_cast<unsigned*>(&o1);
    o.z = *reinterpret_cast<unsigned*>(&o2);
    o.w = *reinterpret_cast<unsigned*>(&o3);
    hcur[n * 8 + q] = o;
}

// ---------------- tensor-core 4-way matmul: out = b + sum_m Xm @ Wm -------------
#define WT_STRIDE 72
__global__ void __launch_bounds__(256) k_mat4_mma(
        const __half* __restrict__ X0, const __half* __restrict__ X1,
        const __half* __restrict__ X2, const __half* __restrict__ X3,
        const float* __restrict__ bias, float* __restrict__ out) {
    __shared__ __half sW[4 * 64 * WT_STRIDE];   // 36864 B
    int tid = threadIdx.x;

    {
        const uint4* srcp = (const uint4*)g_whT;
        uint4* dstp = (uint4*)sW;
        #pragma unroll
        for (int i = 0; i < 9; i++) dstp[tid + i * 256] = srcp[tid + i * 256];
    }
    __syncthreads();

    int warp = tid >> 5;
    int lane = tid & 31;
    int rowbase = blockIdx.x * 128 + warp * 16;
    int r1 = rowbase + (lane >> 2);
    int r2 = r1 + 8;
    int qk = (lane & 3) * 2;
    int lr1 = min(r1, NN - 1);
    int lr2 = min(r2, NN - 1);

    unsigned swbase = (unsigned)__cvta_generic_to_shared(sW);
    unsigned rowptr = swbase + (lane & 7) * 144 + ((lane >> 3) & 1) * 16
                    + ((lane >> 4) & 1) * 1152;

    float c[8][4];
    #pragma unroll
    for (int nt = 0; nt < 8; nt++) {
        float2 bv = *reinterpret_cast<const float2*>(&bias[nt * 8 + qk]);
        c[nt][0] = bv.x; c[nt][1] = bv.y; c[nt][2] = bv.x; c[nt][3] = bv.y;
    }

    const __half* Xs[4] = {X0, X1, X2, X3};
    #pragma unroll
    for (int m = 0; m < 4; m++) {
        const __half* Xm = Xs[m];
        unsigned mbase = rowptr + m * 9216;
        #pragma unroll
        for (int ks = 0; ks < 4; ks++) {
            unsigned a0 = *reinterpret_cast<const unsigned*>(&Xm[lr1 * 64 + ks * 16 + qk]);
            unsigned a1 = *reinterpret_cast<const unsigned*>(&Xm[lr2 * 64 + ks * 16 + qk]);
            unsigned a2 = *reinterpret_cast<const unsigned*>(&Xm[lr1 * 64 + ks * 16 + qk + 8]);
            unsigned a3 = *reinterpret_cast<const unsigned*>(&Xm[lr2 * 64 + ks * 16 + qk + 8]);
            #pragma unroll
            for (int np = 0; np < 4; np++) {
                unsigned b0, b1, b2, b3;
                unsigned addr = mbase + np * 2304 + ks * 32;
                asm volatile(
                    "ldmatrix.sync.aligned.m8n8.x4.shared.b16 {%0,%1,%2,%3}, [%4];"
                    : "=r"(b0), "=r"(b1), "=r"(b2), "=r"(b3) : "r"(addr));
                int nt = np * 2;
                asm volatile(
                    "mma.sync.aligned.m16n8k16.row.col.f32.f16.f16.f32 "
                    "{%0,%1,%2,%3}, {%4,%5,%6,%7}, {%8,%9}, {%0,%1,%2,%3};"
                    : "+f"(c[nt][0]), "+f"(c[nt][1]), "+f"(c[nt][2]), "+f"(c[nt][3])
                    : "r"(a0), "r"(a1), "r"(a2), "r"(a3), "r"(b0), "r"(b1));
                asm volatile(
                    "mma.sync.aligned.m16n8k16.row.col.f32.f16.f16.f32 "
                    "{%0,%1,%2,%3}, {%4,%5,%6,%7}, {%8,%9}, {%0,%1,%2,%3};"
                    : "+f"(c[nt+1][0]), "+f"(c[nt+1][1]), "+f"(c[nt+1][2]), "+f"(c[nt+1][3])
                    : "r"(a0), "r"(a1), "r"(a2), "r"(a3), "r"(b2), "r"(b3));
            }
        }
    }

    bool s1 = (r1 < NN), s2 = (r2 < NN);
    #pragma unroll
    for (int nt = 0; nt < 8; nt++) {
        if (s1) *reinterpret_cast<float2*>(&out[r1 * 64 + nt * 8 + qk]) =
            make_float2(c[nt][0], c[nt][1]);
        if (s2) *reinterpret_cast<float2*>(&out[r2 * 64 + nt * 8 + qk]) =
            make_float2(c[nt][2], c[nt][3]);
    }
}

// ---------------- GraphNorm stats: 64 rows per block -----------------------------
#define SROWS 64
__global__ void k_stats(const float* __restrict__ out, const int* __restrict__ batch) {
    int f = threadIdx.x & 63;
    int rg = threadIdx.x >> 6;
    int row0 = blockIdx.x * SROWS;
    int rend = min(row0 + SROWS, NN);
    float s = 0.f, sq = 0.f, c = 0.f;
    int curg = -1;
    for (int r = row0 + rg; r < rend; r += 4) {
        int g = batch[r];
        if (g != curg) {
            if (curg >= 0) {
                atomicAdd(&g_sum[curg * 64 + f], s);
                atomicAdd(&g_sumsq[curg * 64 + f], sq);
                if (f == 0) atomicAdd(&g_cnt[curg], c);
            }
            curg = g; s = 0.f; sq = 0.f; c = 0.f;
        }
        float v = out[r * 64 + f];
        s += v; sq += v * v; c += 1.f;
    }
    if (curg >= 0) {
        atomicAdd(&g_sum[curg * 64 + f], s);
        atomicAdd(&g_sumsq[curg * 64 + f], sq);
        if (f == 0) atomicAdd(&g_cnt[curg], c);
    }
}

// ---------------- per-(g,f) scale/shift ------------------------------------------
__global__ void k_prep(const float* __restrict__ gn_w, const float* __restrict__ gn_b,
                       const float* __restrict__ gn_ms) {
    int idx = blockIdx.x * blockDim.x + threadIdx.x;
    if (idx >= G * F) return;
    int g = idx >> 6, f = idx & 63;
    float cnt = fmaxf(g_cnt[g], 1.f);
    float m = g_sum[idx] / cnt;
    float ms = m * gn_ms[f];
    float var = g_sumsq[idx] / cnt - ms * (2.f * m - ms);
    var = fmaxf(var, 0.f);
    float sc = gn_w[f] * rsqrtf(var + EPS);
    g_scale[idx] = sc;
    g_shift[idx] = gn_b[f] - ms * sc;
}

// ---------------- normalize + residual + relu + pooling: 64 rows per block ------
__global__ void k_final(const float* __restrict__ out, const float* __restrict__ x,
                        const int* __restrict__ batch, float* __restrict__ demb) {
    int f = threadIdx.x & 63;
    int rg = threadIdx.x >> 6;
    int row0 = blockIdx.x * SROWS;
    int rend = min(row0 + SROWS, NN);
    float s = 0.f, mx = 0.f;
    int curg = -1;
    float sc = 0.f, sh = 0.f;
    for (int r = row0 + rg; r < rend; r += 4) {
        int g = batch[r];
        if (g != curg) {
            if (curg >= 0) {
                atomicAdd(&g_psum[curg * 64 + f], s);
                atomicMax(reinterpret_cast<int*>(&g_pmax[curg * 64 + f]), __float_as_int(mx));
            }
            curg = g; s = 0.f; mx = 0.f;
            sc = g_scale[g * 64 + f];
            sh = g_shift[g * 64 + f];
        }
        float v = out[r * 64 + f] * sc + sh + x[r * 64 + f];
        v = fmaxf(v, 0.f);
        demb[r * 64 + f] = v;
        s += v;
        mx = fmaxf(mx, v);
    }
    if (curg >= 0) {
        atomicAdd(&g_psum[curg * 64 + f], s);
        atomicMax(reinterpret_cast<int*>(&g_pmax[curg * 64 + f]), __float_as_int(mx));
    }
}

// ---------------- flat output: [G, 2F] ---------------------------------------------
__global__ void k_flat(float* __restrict__ flat) {
    int idx = blockIdx.x * blockDim.x + threadIdx.x;
    if (idx >= G * 2 * F) return;
    int g = idx >> 7, j = idx & 127;
    float cnt = fmaxf(g_cnt[g], 1.f);
    flat[idx] = (j < 64) ? (g_psum[g * 64 + j] / cnt) : g_pmax[g * 64 + (j - 64)];
}

// ---------------- launch -------------------------------------------------------------
extern "C" void kernel_launch(void* const* d_in, const int* in_sizes, int n_in,
                              void* d_out, int out_size) {
    const float* x     = (const float*)d_in[0];
    const int*   ei    = (const int*)d_in[1];
    const int*   batch = (const int*)d_in[2];
    const float* ew    = (const float*)d_in[3];
    const float* W     = (const float*)d_in[4];
    const float* bias  = (const float*)d_in[5];
    const float* gn_w  = (const float*)d_in[6];
    const float* gn_b  = (const float*)d_in[7];
    const float* gn_ms = (const float*)d_in[8];

    float* demb = (float*)d_out;
    float* flat = (float*)d_out + (size_t)NN * F;

    const int* src = ei;
    const int* dst = ei + NE;

    __half *pxh, *ph1, *ph2, *ph3;
    float *pout;
    cudaGetSymbolAddress((void**)&pxh, g_xh);
    cudaGetSymbolAddress((void**)&ph1, g_h1);
    cudaGetSymbolAddress((void**)&ph2, g_h2);
    cudaGetSymbolAddress((void**)&ph3, g_h3);
    cudaGetSymbolAddress((void**)&pout, g_out);

    k_zero<<<256, 256>>>();
    k_deg<<<(NE + 255) / 256, 256>>>(dst, ew, (const float2*)x, W);
    k_offsets<<<(NN + 255) / 256, 256>>>();
    k_scatter<<<(NE + 255) / 256, 256>>>(src, dst, ew);

    int gat_blocks = (NN * 8 + 255) / 256;
    k_gather<<<gat_blocks, 256>>>((const uint4*)pxh, (uint4*)ph1);
    k_gather<<<gat_blocks, 256>>>((const uint4*)ph1, (uint4*)ph2);
    k_gather<<<gat_blocks, 256>>>((const uint4*)ph2, (uint4*)ph3);

    int mat_blocks = (NN + 127) / 128;
    k_mat4_mma<<<mat_blocks, 256>>>(pxh, ph1, ph2, ph3, bias, pout);

    int row_blocks = (NN + SROWS - 1) / SROWS;
    k_stats<<<row_blocks, 256>>>(pout, batch);
    k_prep<<<(G * F + 255) / 256, 256>>>(gn_w, gn_b, gn_ms);
    k_final<<<row_blocks, 256>>>(pout, x, batch, demb);
    k_flat<<<(G * 2 * F + 255) / 256, 256>>>(flat);
}